// round 7
// baseline (speedup 1.0000x reference)
#include <cuda_runtime.h>
#include <cuda_bf16.h>
#include <cstdint>
#include <math.h>

#define BB 64
#define SS 512
#define CC 1024
#define HH 1024
#define G3 3072

// image sizes
#define WTB   196608u    // weight tile: 8 chunks x (BHI 12288 + BLO 12288)
#define AIMG  524288u    // x image per 128-row block: 8 chunks x (AHI 32768 + ALO 32768)
#define HIMG  262144u    // h image per buffer: 8 chunks x (AHI 16384 + ALO 16384)

// ---------------- device globals ----------------
__device__ __align__(16) float   d_g0[(size_t)SS * BB * G3];   // layer-0 gi (+bih0), packed [m][ct*48 + g*16+i]
__device__ __align__(16) float   d_h0f[2][BB * HH];
__device__ __align__(16) float   d_h1f[2][BB * HH];
__device__ __align__(16) float   d_gh1[BB * G3];               // layer-1 gh (+bhh1)
__device__ __align__(128) uint8_t d_wimg[256ull * WTB];        // tiles: 0-63 Wih0, 64-127 Whh0, 128-191 Whh1, 192-255 Wih1
__device__ __align__(128) uint8_t d_ximg[256ull * AIMG];
__device__ __align__(128) uint8_t d_himg0[2][HIMG];
__device__ __align__(128) uint8_t d_himg1[2][HIMG];
__device__ unsigned int d_bar_arrive;
__device__ unsigned int d_bar_gen;

// ---------------- helpers ----------------
__device__ __forceinline__ uint32_t smem_u32(const void* p) {
    uint32_t a;
    asm("{ .reg .u64 t; cvta.to.shared.u64 t, %1; cvt.u32.u64 %0, t; }" : "=r"(a) : "l"(p));
    return a;
}
__device__ __forceinline__ void cp_async16(uint32_t s, const void* g) {
    asm volatile("cp.async.cg.shared.global [%0], [%1], 16;" :: "r"(s), "l"(g));
}
#define CP_COMMIT() asm volatile("cp.async.commit_group;" ::: "memory")
#define CP_WAIT1()  asm volatile("cp.async.wait_group 1;" ::: "memory")
#define CP_WAIT0()  asm volatile("cp.async.wait_group 0;" ::: "memory")

__device__ __forceinline__ void mma16816(float (&d)[4], const uint32_t* a, const uint32_t* b) {
    asm volatile("mma.sync.aligned.m16n8k16.row.col.f32.bf16.bf16.f32 "
        "{%0,%1,%2,%3}, {%4,%5,%6,%7}, {%8,%9}, {%0,%1,%2,%3};"
        : "+f"(d[0]), "+f"(d[1]), "+f"(d[2]), "+f"(d[3])
        : "r"(a[0]), "r"(a[1]), "r"(a[2]), "r"(a[3]), "r"(b[0]), "r"(b[1]));
}

__device__ __forceinline__ void cvt2(float a, float b, uint32_t& hi, uint32_t& lo) {
    __nv_bfloat162 h = __floats2bfloat162_rn(a, b);
    float2 f = __bfloat1622float2(h);
    __nv_bfloat162 l = __floats2bfloat162_rn(a - f.x, b - f.y);
    hi = *(uint32_t*)&h;
    lo = *(uint32_t*)&l;
}
__device__ __forceinline__ float sigm(float x) { return 1.0f / (1.0f + __expf(-x)); }

// ---------------- grid barrier (validated in R1/R3) ----------------
__device__ __forceinline__ void grid_sync(int nblocks) {
    __syncthreads();
    if (threadIdx.x == 0) {
        __threadfence();
        unsigned int gen = *((volatile unsigned int*)&d_bar_gen);
        if (atomicAdd(&d_bar_arrive, 1u) == (unsigned int)(nblocks - 1)) {
            atomicExch(&d_bar_arrive, 0u);
            __threadfence();
            atomicExch(&d_bar_gen, gen + 1u);
        } else {
            while (*((volatile unsigned int*)&d_bar_gen) == gen) { __nanosleep(64); }
        }
        __threadfence();
    }
    __syncthreads();
}

// ---------------- fragment compute: 6 n-tiles x 8 k-steps x 3 passes ----------------
template <bool M128>
__device__ __forceinline__ void compute_chunk(char* buf, float (&acc)[6][4], int w, int lane) {
    constexpr int APLANE = M128 ? 32768 : 16384;
    char* aph = buf + w * 4096 + lane * 16;
    char* apl = aph + APLANE;
    char* bp  = buf + 2 * APLANE + lane * 8;
#pragma unroll
    for (int ks = 0; ks < 8; ks++) {
        uint32_t ah[4], al[4];
        *(uint4*)ah = *(const uint4*)(aph + ks * 512);
        *(uint4*)al = *(const uint4*)(apl + ks * 512);
#pragma unroll
        for (int nt = 0; nt < 6; nt++) {
            uint32_t bh[2], bl[2];
            *(uint2*)bh = *(const uint2*)(bp + nt * 2048 + ks * 256);
            *(uint2*)bl = *(const uint2*)(bp + 12288 + nt * 2048 + ks * 256);
            mma16816(acc[nt], ah, bh);
            mma16816(acc[nt], ah, bl);
            mma16816(acc[nt], al, bh);
        }
    }
}

// ---------------- one GEMM job with fused epilogue ----------------
// MODE 0: layer0 update (acc=gh, gsrc=gi)   MODE 1: layer1 gh raw (+bhh1) -> outg
// MODE 2: layer1 update (acc=gi, gsrc=gh)   MODE 3: phase A (M=128) -> outg (+bih0)
template <int MODE>
__device__ void run_job(char* smem, uint32_t sb,
                        const uint8_t* __restrict__ aimg, const uint8_t* __restrict__ wimg,
                        const float* __restrict__ bias, int ct,
                        const float* __restrict__ gsrc, const float* __restrict__ hprevf,
                        float* __restrict__ houtf, uint8_t* __restrict__ himg_out,
                        float* __restrict__ outg) {
    constexpr bool M128 = (MODE == 3);
    constexpr int ABYTES = M128 ? 65536 : 32768;
    constexpr int BUFB = ABYTES + 24576;
    const int tid = threadIdx.x, w = tid >> 5, lane = tid & 31;

    // chunk 0 copy
    for (int i = tid * 16; i < ABYTES; i += 4096) cp_async16(sb + i, aimg + i);
    for (int i = tid * 16; i < 24576; i += 4096) cp_async16(sb + ABYTES + i, wimg + i);
    CP_COMMIT();

    float acc[6][4];
#pragma unroll
    for (int n = 0; n < 6; n++)
#pragma unroll
        for (int q = 0; q < 4; q++) acc[n][q] = 0.f;

    for (int c = 0; c < 8; c++) {
        if (c < 7) {
            const uint32_t db = sb + ((c + 1) & 1) * BUFB;
            const uint8_t* as = aimg + (size_t)(c + 1) * ABYTES;
            for (int i = tid * 16; i < ABYTES; i += 4096) cp_async16(db + i, as + i);
            const uint8_t* bs = wimg + (size_t)(c + 1) * 24576;
            for (int i = tid * 16; i < 24576; i += 4096) cp_async16(db + ABYTES + i, bs + i);
            CP_COMMIT();
            CP_WAIT1();
        } else {
            CP_WAIT0();
        }
        __syncthreads();
        if (M128 || w < 4) compute_chunk<M128>(smem + (c & 1) * BUFB, acc, w, lane);
        __syncthreads();
    }

    if (M128 || w < 4) {
        const int r0 = w * 16 + (lane >> 2), r1 = r0 + 8;
        const int cb = ct * 48, hb16 = ct * 16;

        if (MODE == 1 || MODE == 3) {
#pragma unroll
            for (int nt = 0; nt < 6; nt++) {
                const int g = nt >> 1, i = (nt & 1) * 8 + (lane & 3) * 2;
                float2 bs = *(const float2*)(bias + g * HH + hb16 + i);
                *(float2*)(outg + (size_t)r0 * G3 + cb + nt * 8 + (lane & 3) * 2) =
                    make_float2(acc[nt][0] + bs.x, acc[nt][1] + bs.y);
                *(float2*)(outg + (size_t)r1 * G3 + cb + nt * 8 + (lane & 3) * 2) =
                    make_float2(acc[nt][2] + bs.x, acc[nt][3] + bs.y);
            }
        } else {
            const uint32_t chb = (uint32_t)(ct >> 3) * 32768u + (uint32_t)(ct & 7) * 512u +
                                 (uint32_t)w * 4096u + (uint32_t)((lane >> 2) * 4 + (lane & 3)) * 16u;
#pragma unroll
            for (int ntb = 0; ntb < 2; ntb++) {
                const int i = ntb * 8 + (lane & 3) * 2;
                float2 br = *(const float2*)(bias + hb16 + i);
                float2 bz = *(const float2*)(bias + HH + hb16 + i);
                float2 bn = *(const float2*)(bias + 2 * HH + hb16 + i);
#pragma unroll
                for (int rs = 0; rs < 2; rs++) {
                    const int row = rs ? r1 : r0;
                    const int di = rs * 2;
                    float a_r0 = acc[ntb][di] + br.x,     a_r1 = acc[ntb][di + 1] + br.y;
                    float a_z0 = acc[2 + ntb][di] + bz.x, a_z1 = acc[2 + ntb][di + 1] + bz.y;
                    float a_n0 = acc[4 + ntb][di] + bn.x, a_n1 = acc[4 + ntb][di + 1] + bn.y;
                    const float* gp = gsrc + (size_t)row * G3 + cb;
                    float2 gr = *(const float2*)(gp + i);
                    float2 gz = *(const float2*)(gp + 16 + i);
                    float2 gn = *(const float2*)(gp + 32 + i);
                    float ir0, iz0, in0, hr0, hz0, hn0, ir1, iz1, in1, hr1, hz1, hn1;
                    if (MODE == 0) {
                        ir0 = gr.x; iz0 = gz.x; in0 = gn.x; hr0 = a_r0; hz0 = a_z0; hn0 = a_n0;
                        ir1 = gr.y; iz1 = gz.y; in1 = gn.y; hr1 = a_r1; hz1 = a_z1; hn1 = a_n1;
                    } else {
                        hr0 = gr.x; hz0 = gz.x; hn0 = gn.x; ir0 = a_r0; iz0 = a_z0; in0 = a_n0;
                        hr1 = gr.y; hz1 = gz.y; hn1 = gn.y; ir1 = a_r1; iz1 = a_z1; in1 = a_n1;
                    }
                    float rr0 = sigm(ir0 + hr0), zz0 = sigm(iz0 + hz0);
                    float rr1 = sigm(ir1 + hr1), zz1 = sigm(iz1 + hz1);
                    float nn0 = tanhf(in0 + rr0 * hn0);
                    float nn1 = tanhf(in1 + rr1 * hn1);
                    float2 hp = *(const float2*)(hprevf + (size_t)row * HH + hb16 + i);
                    float h0v = (1.f - zz0) * nn0 + zz0 * hp.x;
                    float h1v = (1.f - zz1) * nn1 + zz1 * hp.y;
                    *(float2*)(houtf + (size_t)row * HH + hb16 + i) = make_float2(h0v, h1v);
                    uint32_t hb, lb;
                    cvt2(h0v, h1v, hb, lb);
                    const uint32_t ea = chb + (uint32_t)(rs + 2 * ntb) * 4u;
                    *(uint32_t*)(himg_out + ea) = hb;
                    *(uint32_t*)(himg_out + 16384 + ea) = lb;
                }
            }
        }
    }
    __syncthreads();   // hardened: uniform re-convergence before any subsequent job touches smem
}

// ---------------- prep: weights -> fragment-linear bf16 hi/lo images ----------------
__global__ __launch_bounds__(256) void prep_w(const float* __restrict__ wih, const float* __restrict__ whh) {
    const int tile = blockIdx.x;
    const float* W;
    if (tile < 64)       W = wih;
    else if (tile < 128) W = whh;
    else if (tile < 192) W = whh + (size_t)G3 * HH;
    else                 W = wih + (size_t)G3 * CC;
    const int ct = tile & 63;
    uint8_t* img = d_wimg + (size_t)tile * WTB;
    for (int idx = threadIdx.x; idx < 48 * 512; idx += 256) {
        const int j = idx >> 9, kp = idx & 511, k = kp * 2;
        const int g = j >> 4, i2 = j & 15;
        float2 v = *(const float2*)(W + (size_t)(g * HH + ct * 16 + i2) * CC + k);
        uint32_t hb, lb;
        cvt2(v.x, v.y, hb, lb);
        const int chunk = k >> 7, ks = (k >> 4) & 7, kk = k & 15;
        const int nt = j >> 3, n8 = j & 7;
        const uint32_t off = (uint32_t)chunk * 24576u + (uint32_t)nt * 2048u + (uint32_t)ks * 256u +
                             (uint32_t)(n8 * 4 + ((kk & 7) >> 1)) * 8u + (uint32_t)(kk >> 3) * 4u;
        *(uint32_t*)(img + off) = hb;
        *(uint32_t*)(img + off + 12288) = lb;
    }
}

// ---------------- prep: x -> fragment-linear A images ----------------
__global__ __launch_bounds__(256) void prep_x(const float* __restrict__ x) {
    const int mb = blockIdx.x >> 3, c = blockIdx.x & 7;
    uint8_t* img = d_ximg + (size_t)mb * AIMG + (size_t)c * 65536;
    for (int idx = threadIdx.x; idx < 128 * 64; idx += 256) {
        const int row = idx >> 6, kp = idx & 63, k = kp * 2;
        const int m = mb * 128 + row, t = m >> 6, b = m & 63;
        float2 v = *(const float2*)(x + ((size_t)b * SS + t) * CC + c * 128 + k);
        uint32_t hb, lb;
        cvt2(v.x, v.y, hb, lb);
        const int r16 = row >> 4, ks = k >> 4, kk = k & 15;
        const uint32_t off = (uint32_t)r16 * 4096u + (uint32_t)ks * 512u +
                             (uint32_t)((row & 7) * 4 + ((kk & 7) >> 1)) * 16u +
                             (uint32_t)(((row >> 3) & 1) + 2 * (kk >> 3)) * 4u;
        *(uint32_t*)(img + off) = hb;
        *(uint32_t*)(img + off + 32768) = lb;
    }
}

// ---------------- phase A: gi0 = x @ Wih0^T + bih0 ----------------
__global__ __launch_bounds__(256, 1) void gru_phaseA(const float* __restrict__ bih) {
    extern __shared__ char smem[];
    uint32_t sb = smem_u32(smem);
    const int ct = blockIdx.x, mb = blockIdx.y;
    run_job<3>(smem, sb, d_ximg + (size_t)mb * AIMG, d_wimg + (size_t)ct * WTB,
               bih, ct, nullptr, nullptr, nullptr, nullptr,
               d_g0 + (size_t)mb * 128 * G3);
}

// ---------------- phase B: persistent recurrence ----------------
__global__ __launch_bounds__(256, 1) void gru_phaseB(const float* __restrict__ bih,
                                                     const float* __restrict__ bhh,
                                                     float* __restrict__ out) {
    extern __shared__ char smem[];
    uint32_t sb = smem_u32(smem);
    const int nb = gridDim.x, tid = threadIdx.x;
    const int gidx = blockIdx.x * 256 + tid, gs = nb * 256;

    for (int i = gidx; i < BB * HH; i += gs) { d_h0f[0][i] = 0.f; d_h1f[0][i] = 0.f; }
    for (int i = gidx; i < (int)(HIMG / 4); i += gs) {
        ((uint32_t*)d_himg0[0])[i] = 0u;
        ((uint32_t*)d_himg1[0])[i] = 0u;
    }
    grid_sync(nb);

    for (int t = 0; t < SS; t++) {
        const int cur = t & 1, nxt = cur ^ 1;
        for (int job = blockIdx.x; job < 128; job += nb) {
            const int ct = job & 63;
            if (job < 64)
                run_job<0>(smem, sb, d_himg0[cur], d_wimg + (size_t)(64 + ct) * WTB,
                           bhh, ct, d_g0 + (size_t)t * BB * G3, d_h0f[cur], d_h0f[nxt],
                           d_himg0[nxt], nullptr);
            else
                run_job<1>(smem, sb, d_himg1[cur], d_wimg + (size_t)(128 + ct) * WTB,
                           bhh + G3, ct, nullptr, nullptr, nullptr, nullptr, d_gh1);
        }
        grid_sync(nb);
        for (int job = blockIdx.x; job < 64; job += nb)
            run_job<2>(smem, sb, d_himg0[nxt], d_wimg + (size_t)(192 + job) * WTB,
                       bih + G3, job, d_gh1, d_h1f[cur], d_h1f[nxt], d_himg1[nxt], nullptr);
        grid_sync(nb);
    }
    for (int i = gidx; i < BB * HH; i += gs) out[i] = d_h1f[0][i];
}

// ---------------- host launcher ----------------
#define PB_SMEM (2 * (32768 + 24576))   // 114688
#define PA_SMEM (2 * (65536 + 24576))   // 180224

extern "C" void kernel_launch(void* const* d_in, const int* in_sizes, int n_in,
                              void* d_out, int out_size) {
    const float* x   = (const float*)d_in[0];
    const float* wih = (const float*)d_in[1];
    const float* whh = (const float*)d_in[2];
    const float* bih = (const float*)d_in[3];
    const float* bhh = (const float*)d_in[4];
    float* out = (float*)d_out;

    cudaFuncSetAttribute(gru_phaseA, cudaFuncAttributeMaxDynamicSharedMemorySize, PA_SMEM);
    cudaFuncSetAttribute(gru_phaseB, cudaFuncAttributeMaxDynamicSharedMemorySize, PB_SMEM);

    int nsm = 0;
    cudaDeviceGetAttribute(&nsm, cudaDevAttrMultiProcessorCount, 0);
    if (nsm <= 0) nsm = 148;

    prep_w<<<256, 256>>>(wih, whh);
    prep_x<<<2048, 256>>>(x);
    gru_phaseA<<<dim3(64, 256), 256, PA_SMEM>>>(bih);
    gru_phaseB<<<nsm, 256, PB_SMEM>>>(bih, bhh, out);
}

// round 10
// speedup vs baseline: 1.0169x; 1.0169x over previous
#include <cuda_runtime.h>
#include <cuda_bf16.h>
#include <cstdint>
#include <math.h>

#define BB 64
#define SS 512
#define CC 1024
#define HH 1024
#define G3 3072

#define WTB   196608u
#define AIMG  524288u
#define HIMG  262144u

#define SLOB  98304u                    // phase-B staging base (after 96KB resident W1-hi)
#define PB_SMEM (98304 + 49152)         // 147456 = 144KB
#define SLOA  98304u
#define PA_SMEM (98304 + 24576)         // 120KB

__device__ __align__(16) float   d_g0[(size_t)SS * BB * G3];
__device__ __align__(16) float   d_h0f[2][BB * HH];
__device__ __align__(16) float   d_h1f[2][BB * HH];
__device__ __align__(16) float   d_gh1[BB * G3];
__device__ __align__(128) uint8_t d_wimg[256ull * WTB];   // 0-63 Wih0 | 64-127 Whh0 | 128-191 Whh1 | 192-255 Wih1
__device__ __align__(128) uint8_t d_ximg[256ull * AIMG];
__device__ __align__(128) uint8_t d_himg0[2][HIMG];
__device__ __align__(128) uint8_t d_himg1[2][HIMG];
__device__ unsigned int d_bar[1032];    // monotonic per-event barrier counters

__device__ __forceinline__ uint32_t smem_u32(const void* p) {
    uint32_t a;
    asm("{ .reg .u64 t; cvta.to.shared.u64 t, %1; cvt.u32.u64 %0, t; }" : "=r"(a) : "l"(p));
    return a;
}
__device__ __forceinline__ void cp_async16(uint32_t s, const void* g) {
    asm volatile("cp.async.cg.shared.global [%0], [%1], 16;" :: "r"(s), "l"(g));
}
#define CP_COMMIT() asm volatile("cp.async.commit_group;" ::: "memory")
#define CP_WAIT1()  asm volatile("cp.async.wait_group 1;" ::: "memory")
#define CP_WAIT0()  asm volatile("cp.async.wait_group 0;" ::: "memory")

__device__ __forceinline__ void mma16816(float (&d)[4], const uint32_t* a, const uint32_t* b) {
    asm volatile("mma.sync.aligned.m16n8k16.row.col.f32.bf16.bf16.f32 "
        "{%0,%1,%2,%3}, {%4,%5,%6,%7}, {%8,%9}, {%0,%1,%2,%3};"
        : "+f"(d[0]), "+f"(d[1]), "+f"(d[2]), "+f"(d[3])
        : "r"(a[0]), "r"(a[1]), "r"(a[2]), "r"(a[3]), "r"(b[0]), "r"(b[1]));
}
__device__ __forceinline__ void cvt2(float a, float b, uint32_t& hi, uint32_t& lo) {
    __nv_bfloat162 h = __floats2bfloat162_rn(a, b);
    float2 f = __bfloat1622float2(h);
    __nv_bfloat162 l = __floats2bfloat162_rn(a - f.x, b - f.y);
    hi = *(uint32_t*)&h;
    lo = *(uint32_t*)&l;
}
__device__ __forceinline__ float sigm(float x) { return 1.0f / (1.0f + __expf(-x)); }

// monotonic barrier: slot counters zeroed by bar_reset before phaseB each launch
__device__ __forceinline__ void grid_sync_slot(int slot, unsigned int nb) {
    __syncthreads();
    if (threadIdx.x == 0) {
        __threadfence();                                   // publish our writes
        atomicAdd(&d_bar[slot], 1u);
        while (*((volatile unsigned int*)&d_bar[slot]) < nb) { __nanosleep(64); }
        __threadfence();                                   // acquire others' writes
    }
    __syncthreads();
}

// ---- GEMM M=64, W-hi RESIDENT at smem[0..96KB), W-lo staged (2x12KB) ----
__device__ __forceinline__ void gemm64_res(char* smem, uint32_t sb,
        const uint8_t* __restrict__ aimg, const uint8_t* __restrict__ wtile,
        float (&acc)[3][4], int mtile, int ihalf, int lane) {
    const int tid = threadIdx.x;
    const uint32_t t16 = (uint32_t)lane * 16u, t8 = (uint32_t)lane * 8u;
    for (int i = tid * 16; i < 12288; i += 4096) cp_async16(sb + SLOB + i, wtile + 12288 + i);
    CP_COMMIT();
    for (int c = 0; c < 8; c++) {
        if (c) __syncthreads();
        if (c < 7) {
            const uint8_t* src = wtile + (size_t)(c + 1) * 24576 + 12288;
            uint32_t dst = sb + SLOB + (uint32_t)((c + 1) & 1) * 12288u;
            for (int i = tid * 16; i < 12288; i += 4096) cp_async16(dst + i, src + i);
            CP_COMMIT();
        }
        uint4 AH[8], AL[8];
        const uint8_t* ab = aimg + (size_t)c * 32768 + (uint32_t)mtile * 4096u + t16;
#pragma unroll
        for (int ks = 0; ks < 8; ks++) {
            AH[ks] = *(const uint4*)(ab + ks * 512);
            AL[ks] = *(const uint4*)(ab + 16384 + ks * 512);
        }
        if (c < 7) { CP_WAIT1(); } else { CP_WAIT0(); }
        __syncthreads();
        const char* wb = smem + c * 12288;
        const char* lb = smem + SLOB + (c & 1) * 12288;
#pragma unroll
        for (int ks = 0; ks < 8; ks++) {
#pragma unroll
            for (int j = 0; j < 3; j++) {
                const int nt = 2 * j + ihalf;
                uint32_t bh[2], bl[2];
                *(uint2*)bh = *(const uint2*)(wb + nt * 2048 + ks * 256 + t8);
                *(uint2*)bl = *(const uint2*)(lb + nt * 2048 + ks * 256 + t8);
                mma16816(acc[j], (const uint32_t*)&AH[ks], bh);
                mma16816(acc[j], (const uint32_t*)&AH[ks], bl);
                mma16816(acc[j], (const uint32_t*)&AL[ks], bh);
            }
        }
    }
    __syncthreads();
}

// ---- GEMM M=64, W hi+lo STREAMED (2x24KB staging) ----
__device__ __forceinline__ void gemm64_strm(char* smem, uint32_t sb,
        const uint8_t* __restrict__ aimg, const uint8_t* __restrict__ wtile,
        float (&acc)[3][4], int mtile, int ihalf, int lane) {
    const int tid = threadIdx.x;
    const uint32_t t16 = (uint32_t)lane * 16u, t8 = (uint32_t)lane * 8u;
    for (int i = tid * 16; i < 24576; i += 4096) cp_async16(sb + SLOB + i, wtile + i);
    CP_COMMIT();
    for (int c = 0; c < 8; c++) {
        if (c) __syncthreads();
        if (c < 7) {
            const uint8_t* src = wtile + (size_t)(c + 1) * 24576;
            uint32_t dst = sb + SLOB + (uint32_t)((c + 1) & 1) * 24576u;
            for (int i = tid * 16; i < 24576; i += 4096) cp_async16(dst + i, src + i);
            CP_COMMIT();
        }
        uint4 AH[8], AL[8];
        const uint8_t* ab = aimg + (size_t)c * 32768 + (uint32_t)mtile * 4096u + t16;
#pragma unroll
        for (int ks = 0; ks < 8; ks++) {
            AH[ks] = *(const uint4*)(ab + ks * 512);
            AL[ks] = *(const uint4*)(ab + 16384 + ks * 512);
        }
        if (c < 7) { CP_WAIT1(); } else { CP_WAIT0(); }
        __syncthreads();
        const char* wb = smem + SLOB + (c & 1) * 24576;
        const char* lb = wb + 12288;
#pragma unroll
        for (int ks = 0; ks < 8; ks++) {
#pragma unroll
            for (int j = 0; j < 3; j++) {
                const int nt = 2 * j + ihalf;
                uint32_t bh[2], bl[2];
                *(uint2*)bh = *(const uint2*)(wb + nt * 2048 + ks * 256 + t8);
                *(uint2*)bl = *(const uint2*)(lb + nt * 2048 + ks * 256 + t8);
                mma16816(acc[j], (const uint32_t*)&AH[ks], bh);
                mma16816(acc[j], (const uint32_t*)&AH[ks], bl);
                mma16816(acc[j], (const uint32_t*)&AL[ks], bh);
            }
        }
    }
    __syncthreads();
}

// ---- GEMM M=128 (phase A): W-hi resident, W-lo staged ----
__device__ __forceinline__ void gemm128(char* smem, uint32_t sb,
        const uint8_t* __restrict__ aimg, const uint8_t* __restrict__ wtile,
        float (&acc)[6][4], int w, int lane) {
    const int tid = threadIdx.x;
    const uint32_t t16 = (uint32_t)lane * 16u, t8 = (uint32_t)lane * 8u;
    for (int i = tid * 16; i < 12288; i += 4096) cp_async16(sb + SLOA + i, wtile + 12288 + i);
    CP_COMMIT();
    for (int c = 0; c < 8; c++) {
        if (c) __syncthreads();
        if (c < 7) {
            const uint8_t* src = wtile + (size_t)(c + 1) * 24576 + 12288;
            uint32_t dst = sb + SLOA + (uint32_t)((c + 1) & 1) * 12288u;
            for (int i = tid * 16; i < 12288; i += 4096) cp_async16(dst + i, src + i);
            CP_COMMIT();
        }
        uint4 AH[8], AL[8];
        const uint8_t* ab = aimg + (size_t)c * 65536 + (uint32_t)w * 4096u + t16;
#pragma unroll
        for (int ks = 0; ks < 8; ks++) {
            AH[ks] = *(const uint4*)(ab + ks * 512);
            AL[ks] = *(const uint4*)(ab + 32768 + ks * 512);
        }
        if (c < 7) { CP_WAIT1(); } else { CP_WAIT0(); }
        __syncthreads();
        const char* wb = smem + c * 12288;
        const char* lb = smem + SLOA + (c & 1) * 12288;
#pragma unroll
        for (int ks = 0; ks < 8; ks++) {
#pragma unroll
            for (int nt = 0; nt < 6; nt++) {
                uint32_t bh[2], bl[2];
                *(uint2*)bh = *(const uint2*)(wb + nt * 2048 + ks * 256 + t8);
                *(uint2*)bl = *(const uint2*)(lb + nt * 2048 + ks * 256 + t8);
                mma16816(acc[nt], (const uint32_t*)&AH[ks], bh);
                mma16816(acc[nt], (const uint32_t*)&AH[ks], bl);
                mma16816(acc[nt], (const uint32_t*)&AL[ks], bh);
            }
        }
    }
    __syncthreads();
}

// ---- epilogues ----
template <int ACC_IS_GH>
__device__ __forceinline__ void epi_update(const float (&acc)[3][4],
        const float* __restrict__ gsrc, const float* __restrict__ hprevf,
        float* __restrict__ houtf, uint8_t* __restrict__ himg_out,
        const float* __restrict__ bias, int ct, int mtile, int ihalf, int lane) {
    const int r0 = mtile * 16 + (lane >> 2);
    const int i = ihalf * 8 + (lane & 3) * 2;
    const int hb16 = ct * 16, cb = ct * 48;
    float2 br = *(const float2*)(bias + hb16 + i);
    float2 bz = *(const float2*)(bias + HH + hb16 + i);
    float2 bn = *(const float2*)(bias + 2 * HH + hb16 + i);
    const uint32_t chb = (uint32_t)(ct >> 3) * 32768u + (uint32_t)(ct & 7) * 512u +
                         (uint32_t)mtile * 4096u + (uint32_t)lane * 16u;
#pragma unroll
    for (int rs = 0; rs < 2; rs++) {
        const int row = r0 + rs * 8, di = rs * 2;
        float ar0 = acc[0][di] + br.x, ar1 = acc[0][di + 1] + br.y;
        float az0 = acc[1][di] + bz.x, az1 = acc[1][di + 1] + bz.y;
        float an0 = acc[2][di] + bn.x, an1 = acc[2][di + 1] + bn.y;
        const float* gp = gsrc + (size_t)row * G3 + cb;
        float2 gr = *(const float2*)(gp + i);
        float2 gz = *(const float2*)(gp + 16 + i);
        float2 gn = *(const float2*)(gp + 32 + i);
        float ir0, iz0, in0, hr0, hz0, hn0, ir1, iz1, in1, hr1, hz1, hn1;
        if (ACC_IS_GH) {
            ir0 = gr.x; iz0 = gz.x; in0 = gn.x; hr0 = ar0; hz0 = az0; hn0 = an0;
            ir1 = gr.y; iz1 = gz.y; in1 = gn.y; hr1 = ar1; hz1 = az1; hn1 = an1;
        } else {
            hr0 = gr.x; hz0 = gz.x; hn0 = gn.x; ir0 = ar0; iz0 = az0; in0 = an0;
            hr1 = gr.y; hz1 = gz.y; hn1 = gn.y; ir1 = ar1; iz1 = az1; in1 = an1;
        }
        float rr0 = sigm(ir0 + hr0), zz0 = sigm(iz0 + hz0);
        float rr1 = sigm(ir1 + hr1), zz1 = sigm(iz1 + hz1);
        float nn0 = tanhf(in0 + rr0 * hn0);
        float nn1 = tanhf(in1 + rr1 * hn1);
        float2 hp = *(const float2*)(hprevf + (size_t)row * HH + hb16 + i);
        float h0v = (1.f - zz0) * nn0 + zz0 * hp.x;
        float h1v = (1.f - zz1) * nn1 + zz1 * hp.y;
        *(float2*)(houtf + (size_t)row * HH + hb16 + i) = make_float2(h0v, h1v);
        uint32_t hb, lb;
        cvt2(h0v, h1v, hb, lb);
        const uint32_t ea = chb + (uint32_t)(rs + 2 * ihalf) * 4u;
        *(uint32_t*)(himg_out + ea) = hb;
        *(uint32_t*)(himg_out + 16384 + ea) = lb;
    }
}

__device__ __forceinline__ void epi_raw(const float (&acc)[3][4], float* __restrict__ outg,
        const float* __restrict__ bias, int ct, int mtile, int ihalf, int lane) {
    const int r0 = mtile * 16 + (lane >> 2);
    const int i = ihalf * 8 + (lane & 3) * 2;
    const int hb16 = ct * 16, cb = ct * 48;
#pragma unroll
    for (int j = 0; j < 3; j++) {
        float2 bs = *(const float2*)(bias + j * HH + hb16 + i);
        *(float2*)(outg + (size_t)r0 * G3 + cb + j * 16 + i) =
            make_float2(acc[j][0] + bs.x, acc[j][1] + bs.y);
        *(float2*)(outg + (size_t)(r0 + 8) * G3 + cb + j * 16 + i) =
            make_float2(acc[j][2] + bs.x, acc[j][3] + bs.y);
    }
}

__device__ __forceinline__ void epiA(const float (&acc)[6][4], float* __restrict__ outg,
        const float* __restrict__ bias, int ct, int w, int lane) {
    const int r0 = w * 16 + (lane >> 2);
    const int cb = ct * 48, li2 = (lane & 3) * 2;
#pragma unroll
    for (int nt = 0; nt < 6; nt++) {
        const int g = nt >> 1, i = (nt & 1) * 8 + li2;
        float2 bs = *(const float2*)(bias + g * HH + ct * 16 + i);
        *(float2*)(outg + (size_t)r0 * G3 + cb + nt * 8 + li2) =
            make_float2(acc[nt][0] + bs.x, acc[nt][1] + bs.y);
        *(float2*)(outg + (size_t)(r0 + 8) * G3 + cb + nt * 8 + li2) =
            make_float2(acc[nt][2] + bs.x, acc[nt][3] + bs.y);
    }
}

// ---- prep kernels (layouts validated in R6) ----
__global__ __launch_bounds__(256) void prep_w(const float* __restrict__ wih, const float* __restrict__ whh) {
    const int tile = blockIdx.x;
    const float* W;
    if (tile < 64)       W = wih;
    else if (tile < 128) W = whh;
    else if (tile < 192) W = whh + (size_t)G3 * HH;
    else                 W = wih + (size_t)G3 * CC;
    const int ct = tile & 63;
    uint8_t* img = d_wimg + (size_t)tile * WTB;
    for (int idx = threadIdx.x; idx < 48 * 512; idx += 256) {
        const int j = idx >> 9, kp = idx & 511, k = kp * 2;
        const int g = j >> 4, i2 = j & 15;
        float2 v = *(const float2*)(W + (size_t)(g * HH + ct * 16 + i2) * CC + k);
        uint32_t hb, lb;
        cvt2(v.x, v.y, hb, lb);
        const int chunk = k >> 7, ks = (k >> 4) & 7, kk = k & 15;
        const int nt = j >> 3, n8 = j & 7;
        const uint32_t off = (uint32_t)chunk * 24576u + (uint32_t)nt * 2048u + (uint32_t)ks * 256u +
                             (uint32_t)(n8 * 4 + ((kk & 7) >> 1)) * 8u + (uint32_t)(kk >> 3) * 4u;
        *(uint32_t*)(img + off) = hb;
        *(uint32_t*)(img + off + 12288) = lb;
    }
}

__global__ __launch_bounds__(256) void prep_x(const float* __restrict__ x) {
    const int mb = blockIdx.x >> 3, c = blockIdx.x & 7;
    uint8_t* img = d_ximg + (size_t)mb * AIMG + (size_t)c * 65536;
    for (int idx = threadIdx.x; idx < 128 * 64; idx += 256) {
        const int row = idx >> 6, kp = idx & 63, k = kp * 2;
        const int m = mb * 128 + row, t = m >> 6, b = m & 63;
        float2 v = *(const float2*)(x + ((size_t)b * SS + t) * CC + c * 128 + k);
        uint32_t hb, lb;
        cvt2(v.x, v.y, hb, lb);
        const int r16 = row >> 4, ks = k >> 4, kk = k & 15;
        const uint32_t off = (uint32_t)r16 * 4096u + (uint32_t)ks * 512u +
                             (uint32_t)((row & 7) * 4 + ((kk & 7) >> 1)) * 16u +
                             (uint32_t)(((row >> 3) & 1) + 2 * (kk >> 3)) * 4u;
        *(uint32_t*)(img + off) = hb;
        *(uint32_t*)(img + off + 32768) = lb;
    }
}

__global__ void bar_reset() {
    for (int i = threadIdx.x; i < 1032; i += 256) d_bar[i] = 0u;
}

// ---- phase A ----
__global__ __launch_bounds__(256, 1) void gru_phaseA(const float* __restrict__ bih) {
    extern __shared__ char smem[];
    uint32_t sb = smem_u32(smem);
    const int ct = blockIdx.x, grp = blockIdx.y;
    const int tid = threadIdx.x, w = tid >> 5, lane = tid & 31;
    const uint8_t* wt = d_wimg + (size_t)ct * WTB;
    for (int c = 0; c < 8; c++)
        for (int i = tid * 16; i < 12288; i += 4096)
            cp_async16(sb + c * 12288 + i, wt + (size_t)c * 24576 + i);
    CP_COMMIT(); CP_WAIT0();
    __syncthreads();
    for (int mb = grp * 32; mb < grp * 32 + 32; mb++) {
        float acc[6][4] = {};
        gemm128(smem, sb, d_ximg + (size_t)mb * AIMG, wt, acc, w, lane);
        epiA(acc, d_g0 + (size_t)mb * 128 * G3, bih, ct, w, lane);
    }
}

// ---- phase B: persistent, 128 CTAs, stage-1 weights resident ----
__global__ __launch_bounds__(256, 1) void gru_phaseB(const float* __restrict__ bih,
                                                     const float* __restrict__ bhh,
                                                     float* __restrict__ out) {
    extern __shared__ char smem[];
    uint32_t sb = smem_u32(smem);
    const unsigned int nb = gridDim.x;
    const int tid = threadIdx.x, cta = blockIdx.x;
    const int w = tid >> 5, lane = tid & 31;
    const int mtile = w >> 1, ihalf = w & 1;
    const int ct = cta & 63;

    const uint8_t* wt1 = d_wimg + (size_t)(64 + cta) * WTB;   // Whh0[ct] or Whh1[ct]
    const uint8_t* wt2 = d_wimg + (size_t)(192 + ct) * WTB;   // Wih1[ct] (streamed)
    for (int c = 0; c < 8; c++)
        for (int i = tid * 16; i < 12288; i += 4096)
            cp_async16(sb + c * 12288 + i, wt1 + (size_t)c * 24576 + i);
    CP_COMMIT(); CP_WAIT0();
    __syncthreads();

    const int gidx = cta * 256 + tid, gs = (int)nb * 256;
    for (int i = gidx; i < BB * HH; i += gs) { d_h0f[0][i] = 0.f; d_h1f[0][i] = 0.f; }
    for (int i = gidx; i < (int)(HIMG / 4); i += gs) {
        ((uint32_t*)d_himg0[0])[i] = 0u;
        ((uint32_t*)d_himg1[0])[i] = 0u;
    }
    grid_sync_slot(0, nb);

    for (int t = 0; t < SS; t++) {
        const int cur = t & 1, nxt = cur ^ 1;
        {
            float acc[3][4] = {};
            if (cta < 64) {
                gemm64_res(smem, sb, d_himg0[cur], wt1, acc, mtile, ihalf, lane);
                epi_update<1>(acc, d_g0 + (size_t)t * BB * G3, d_h0f[cur], d_h0f[nxt],
                              d_himg0[nxt], bhh, ct, mtile, ihalf, lane);
            } else {
                gemm64_res(smem, sb, d_himg1[cur], wt1, acc, mtile, ihalf, lane);
                epi_raw(acc, d_gh1, bhh + G3, ct, mtile, ihalf, lane);
            }
        }
        grid_sync_slot(1 + 2 * t, nb);
        if (cta < 64) {
            float acc[3][4] = {};
            gemm64_strm(smem, sb, d_himg0[nxt], wt2, acc, mtile, ihalf, lane);
            epi_update<0>(acc, d_gh1, d_h1f[cur], d_h1f[nxt],
                          d_himg1[nxt], bih + G3, ct, mtile, ihalf, lane);
        }
        grid_sync_slot(2 + 2 * t, nb);
    }
    for (int i = gidx; i < BB * HH; i += gs) out[i] = d_h1f[0][i];
}

// ---- host launcher ----
extern "C" void kernel_launch(void* const* d_in, const int* in_sizes, int n_in,
                              void* d_out, int out_size) {
    const float* x   = (const float*)d_in[0];
    const float* wih = (const float*)d_in[1];
    const float* whh = (const float*)d_in[2];
    const float* bih = (const float*)d_in[3];
    const float* bhh = (const float*)d_in[4];
    float* out = (float*)d_out;

    cudaFuncSetAttribute(gru_phaseA, cudaFuncAttributeMaxDynamicSharedMemorySize, PA_SMEM);
    cudaFuncSetAttribute(gru_phaseB, cudaFuncAttributeMaxDynamicSharedMemorySize, PB_SMEM);

    prep_w<<<256, 256>>>(wih, whh);
    prep_x<<<2048, 256>>>(x);
    bar_reset<<<1, 256>>>();
    gru_phaseA<<<dim3(64, 8), 256, PA_SMEM>>>(bih);
    gru_phaseB<<<128, 256, PB_SMEM>>>(bih, bhh, out);
}

// round 11
// speedup vs baseline: 1.0785x; 1.0605x over previous
#include <cuda_runtime.h>
#include <cuda_bf16.h>
#include <cstdint>
#include <math.h>

#define BB 64
#define SS 512
#define CC 1024
#define HH 1024
#define G3 3072

#define WTB   196608u
#define AIMG  524288u
#define HIMG  262144u

#define PB_SMEM 98304                   // stage-1 W-hi resident only
#define SLOA  98304u
#define PA_SMEM (98304 + 24576)

__device__ __align__(16) float   d_g0[(size_t)SS * BB * G3];
__device__ __align__(16) float   d_h0f[2][BB * HH];
__device__ __align__(16) float   d_h1f[2][BB * HH];
__device__ __align__(16) float   d_gh1[BB * G3];
__device__ __align__(128) uint8_t d_wimg[256ull * WTB];   // 0-63 Wih0 | 64-127 Whh0 | 128-191 Whh1 | 192-255 Wih1
__device__ __align__(128) uint8_t d_ximg[256ull * AIMG];
__device__ __align__(128) uint8_t d_himg0[2][HIMG];
__device__ __align__(128) uint8_t d_himg1[2][HIMG];
__device__ unsigned int d_bar[1032];

__device__ __forceinline__ uint32_t smem_u32(const void* p) {
    uint32_t a;
    asm("{ .reg .u64 t; cvta.to.shared.u64 t, %1; cvt.u32.u64 %0, t; }" : "=r"(a) : "l"(p));
    return a;
}
__device__ __forceinline__ void cp_async16(uint32_t s, const void* g) {
    asm volatile("cp.async.cg.shared.global [%0], [%1], 16;" :: "r"(s), "l"(g));
}
#define CP_COMMIT() asm volatile("cp.async.commit_group;" ::: "memory")
#define CP_WAIT1()  asm volatile("cp.async.wait_group 1;" ::: "memory")
#define CP_WAIT0()  asm volatile("cp.async.wait_group 0;" ::: "memory")

__device__ __forceinline__ void mma16816(float (&d)[4], const uint32_t* a, const uint32_t* b) {
    asm volatile("mma.sync.aligned.m16n8k16.row.col.f32.bf16.bf16.f32 "
        "{%0,%1,%2,%3}, {%4,%5,%6,%7}, {%8,%9}, {%0,%1,%2,%3};"
        : "+f"(d[0]), "+f"(d[1]), "+f"(d[2]), "+f"(d[3])
        : "r"(a[0]), "r"(a[1]), "r"(a[2]), "r"(a[3]), "r"(b[0]), "r"(b[1]));
}
__device__ __forceinline__ void cvt2(float a, float b, uint32_t& hi, uint32_t& lo) {
    __nv_bfloat162 h = __floats2bfloat162_rn(a, b);
    float2 f = __bfloat1622float2(h);
    __nv_bfloat162 l = __floats2bfloat162_rn(a - f.x, b - f.y);
    hi = *(uint32_t*)&h;
    lo = *(uint32_t*)&l;
}
__device__ __forceinline__ float sigm(float x) { return 1.0f / (1.0f + __expf(-x)); }

__device__ __forceinline__ void grid_sync_slot(int slot, unsigned int nb) {
    __syncthreads();
    if (threadIdx.x == 0) {
        __threadfence();
        atomicAdd(&d_bar[slot], 1u);
        while (*((volatile unsigned int*)&d_bar[slot]) < nb) { __nanosleep(64); }
        __threadfence();
    }
    __syncthreads();
}

// ---- GEMM M=64, zero cp.async. RES: W-hi from resident smem; else W-hi via LDG. ----
template <bool RES>
__device__ __forceinline__ void gemm64_v2(const char* smem, const uint8_t* __restrict__ aimg,
        const uint8_t* __restrict__ wtile, float (&acc)[3][4], int mtile, int ihalf, int lane) {
    const uint32_t t16 = (uint32_t)lane * 16u, t8 = (uint32_t)lane * 8u;
    float a2[2][3][4];
#pragma unroll
    for (int p = 0; p < 2; p++)
#pragma unroll
        for (int j = 0; j < 3; j++)
#pragma unroll
            for (int q = 0; q < 4; q++) a2[p][j][q] = 0.f;

#pragma unroll 1
    for (int c = 0; c < 8; c++) {
        const uint8_t* ab = aimg + (size_t)c * 32768 + (uint32_t)mtile * 4096u + t16;
        const uint8_t* wb = wtile + (size_t)c * 24576 + (uint32_t)ihalf * 2048u + t8;
        const char*    rb = smem + c * 12288 + (uint32_t)ihalf * 2048u + t8;
        uint4 AH[8], AL[8];
        uint2 BH[8][3], BL[8][3];
#pragma unroll
        for (int ks = 0; ks < 8; ks++) {
            AH[ks] = *(const uint4*)(ab + ks * 512);
            AL[ks] = *(const uint4*)(ab + 16384 + ks * 512);
        }
#pragma unroll
        for (int ks = 0; ks < 8; ks++)
#pragma unroll
            for (int j = 0; j < 3; j++) {
                BL[ks][j] = *(const uint2*)(wb + 12288 + j * 4096 + ks * 256);
                if (RES) BH[ks][j] = *(const uint2*)(rb + j * 4096 + ks * 256);
                else     BH[ks][j] = *(const uint2*)(wb + j * 4096 + ks * 256);
            }
#pragma unroll
        for (int ks = 0; ks < 8; ks++) {
            const int p = ks & 1;
#pragma unroll
            for (int j = 0; j < 3; j++) {
                mma16816(a2[p][j], (const uint32_t*)&AH[ks], (const uint32_t*)&BH[ks][j]);
                mma16816(a2[p][j], (const uint32_t*)&AH[ks], (const uint32_t*)&BL[ks][j]);
                mma16816(a2[p][j], (const uint32_t*)&AL[ks], (const uint32_t*)&BH[ks][j]);
            }
        }
    }
#pragma unroll
    for (int j = 0; j < 3; j++)
#pragma unroll
        for (int q = 0; q < 4; q++) acc[j][q] = a2[0][j][q] + a2[1][j][q];
}

// ---- GEMM M=128 (phase A, unchanged from R10) ----
__device__ __forceinline__ void gemm128(char* smem, uint32_t sb,
        const uint8_t* __restrict__ aimg, const uint8_t* __restrict__ wtile,
        float (&acc)[6][4], int w, int lane) {
    const int tid = threadIdx.x;
    const uint32_t t16 = (uint32_t)lane * 16u, t8 = (uint32_t)lane * 8u;
    for (int i = tid * 16; i < 12288; i += 4096) cp_async16(sb + SLOA + i, wtile + 12288 + i);
    CP_COMMIT();
    for (int c = 0; c < 8; c++) {
        if (c) __syncthreads();
        if (c < 7) {
            const uint8_t* src = wtile + (size_t)(c + 1) * 24576 + 12288;
            uint32_t dst = sb + SLOA + (uint32_t)((c + 1) & 1) * 12288u;
            for (int i = tid * 16; i < 12288; i += 4096) cp_async16(dst + i, src + i);
            CP_COMMIT();
        }
        uint4 AH[8], AL[8];
        const uint8_t* ab = aimg + (size_t)c * 65536 + (uint32_t)w * 4096u + t16;
#pragma unroll
        for (int ks = 0; ks < 8; ks++) {
            AH[ks] = *(const uint4*)(ab + ks * 512);
            AL[ks] = *(const uint4*)(ab + 32768 + ks * 512);
        }
        if (c < 7) { CP_WAIT1(); } else { CP_WAIT0(); }
        __syncthreads();
        const char* wb = smem + c * 12288;
        const char* lb = smem + SLOA + (c & 1) * 12288;
#pragma unroll
        for (int ks = 0; ks < 8; ks++) {
#pragma unroll
            for (int nt = 0; nt < 6; nt++) {
                uint32_t bh[2], bl[2];
                *(uint2*)bh = *(const uint2*)(wb + nt * 2048 + ks * 256 + t8);
                *(uint2*)bl = *(const uint2*)(lb + nt * 2048 + ks * 256 + t8);
                mma16816(acc[nt], (const uint32_t*)&AH[ks], bh);
                mma16816(acc[nt], (const uint32_t*)&AH[ks], bl);
                mma16816(acc[nt], (const uint32_t*)&AL[ks], bh);
            }
        }
    }
    __syncthreads();
}

// ---- epilogues (unchanged) ----
template <int ACC_IS_GH>
__device__ __forceinline__ void epi_update(const float (&acc)[3][4],
        const float* __restrict__ gsrc, const float* __restrict__ hprevf,
        float* __restrict__ houtf, uint8_t* __restrict__ himg_out,
        const float* __restrict__ bias, int ct, int mtile, int ihalf, int lane) {
    const int r0 = mtile * 16 + (lane >> 2);
    const int i = ihalf * 8 + (lane & 3) * 2;
    const int hb16 = ct * 16, cb = ct * 48;
    float2 br = *(const float2*)(bias + hb16 + i);
    float2 bz = *(const float2*)(bias + HH + hb16 + i);
    float2 bn = *(const float2*)(bias + 2 * HH + hb16 + i);
    const uint32_t chb = (uint32_t)(ct >> 3) * 32768u + (uint32_t)(ct & 7) * 512u +
                         (uint32_t)mtile * 4096u + (uint32_t)lane * 16u;
#pragma unroll
    for (int rs = 0; rs < 2; rs++) {
        const int row = r0 + rs * 8, di = rs * 2;
        float ar0 = acc[0][di] + br.x, ar1 = acc[0][di + 1] + br.y;
        float az0 = acc[1][di] + bz.x, az1 = acc[1][di + 1] + bz.y;
        float an0 = acc[2][di] + bn.x, an1 = acc[2][di + 1] + bn.y;
        const float* gp = gsrc + (size_t)row * G3 + cb;
        float2 gr = *(const float2*)(gp + i);
        float2 gz = *(const float2*)(gp + 16 + i);
        float2 gn = *(const float2*)(gp + 32 + i);
        float ir0, iz0, in0, hr0, hz0, hn0, ir1, iz1, in1, hr1, hz1, hn1;
        if (ACC_IS_GH) {
            ir0 = gr.x; iz0 = gz.x; in0 = gn.x; hr0 = ar0; hz0 = az0; hn0 = an0;
            ir1 = gr.y; iz1 = gz.y; in1 = gn.y; hr1 = ar1; hz1 = az1; hn1 = an1;
        } else {
            hr0 = gr.x; hz0 = gz.x; hn0 = gn.x; ir0 = ar0; iz0 = az0; in0 = an0;
            hr1 = gr.y; hz1 = gz.y; hn1 = gn.y; ir1 = ar1; iz1 = az1; in1 = an1;
        }
        float rr0 = sigm(ir0 + hr0), zz0 = sigm(iz0 + hz0);
        float rr1 = sigm(ir1 + hr1), zz1 = sigm(iz1 + hz1);
        float nn0 = tanhf(in0 + rr0 * hn0);
        float nn1 = tanhf(in1 + rr1 * hn1);
        float2 hp = *(const float2*)(hprevf + (size_t)row * HH + hb16 + i);
        float h0v = (1.f - zz0) * nn0 + zz0 * hp.x;
        float h1v = (1.f - zz1) * nn1 + zz1 * hp.y;
        *(float2*)(houtf + (size_t)row * HH + hb16 + i) = make_float2(h0v, h1v);
        uint32_t hb, lb;
        cvt2(h0v, h1v, hb, lb);
        const uint32_t ea = chb + (uint32_t)(rs + 2 * ihalf) * 4u;
        *(uint32_t*)(himg_out + ea) = hb;
        *(uint32_t*)(himg_out + 16384 + ea) = lb;
    }
}

__device__ __forceinline__ void epi_raw(const float (&acc)[3][4], float* __restrict__ outg,
        const float* __restrict__ bias, int ct, int mtile, int ihalf, int lane) {
    const int r0 = mtile * 16 + (lane >> 2);
    const int i = ihalf * 8 + (lane & 3) * 2;
    const int hb16 = ct * 16, cb = ct * 48;
#pragma unroll
    for (int j = 0; j < 3; j++) {
        float2 bs = *(const float2*)(bias + j * HH + hb16 + i);
        *(float2*)(outg + (size_t)r0 * G3 + cb + j * 16 + i) =
            make_float2(acc[j][0] + bs.x, acc[j][1] + bs.y);
        *(float2*)(outg + (size_t)(r0 + 8) * G3 + cb + j * 16 + i) =
            make_float2(acc[j][2] + bs.x, acc[j][3] + bs.y);
    }
}

__device__ __forceinline__ void epiA(const float (&acc)[6][4], float* __restrict__ outg,
        const float* __restrict__ bias, int ct, int w, int lane) {
    const int r0 = w * 16 + (lane >> 2);
    const int cb = ct * 48, li2 = (lane & 3) * 2;
#pragma unroll
    for (int nt = 0; nt < 6; nt++) {
        const int g = nt >> 1, i = (nt & 1) * 8 + li2;
        float2 bs = *(const float2*)(bias + g * HH + ct * 16 + i);
        *(float2*)(outg + (size_t)r0 * G3 + cb + nt * 8 + li2) =
            make_float2(acc[nt][0] + bs.x, acc[nt][1] + bs.y);
        *(float2*)(outg + (size_t)(r0 + 8) * G3 + cb + nt * 8 + li2) =
            make_float2(acc[nt][2] + bs.x, acc[nt][3] + bs.y);
    }
}

// ---- prep kernels (unchanged, R6-validated layouts) ----
__global__ __launch_bounds__(256) void prep_w(const float* __restrict__ wih, const float* __restrict__ whh) {
    const int tile = blockIdx.x;
    const float* W;
    if (tile < 64)       W = wih;
    else if (tile < 128) W = whh;
    else if (tile < 192) W = whh + (size_t)G3 * HH;
    else                 W = wih + (size_t)G3 * CC;
    const int ct = tile & 63;
    uint8_t* img = d_wimg + (size_t)tile * WTB;
    for (int idx = threadIdx.x; idx < 48 * 512; idx += 256) {
        const int j = idx >> 9, kp = idx & 511, k = kp * 2;
        const int g = j >> 4, i2 = j & 15;
        float2 v = *(const float2*)(W + (size_t)(g * HH + ct * 16 + i2) * CC + k);
        uint32_t hb, lb;
        cvt2(v.x, v.y, hb, lb);
        const int chunk = k >> 7, ks = (k >> 4) & 7, kk = k & 15;
        const int nt = j >> 3, n8 = j & 7;
        const uint32_t off = (uint32_t)chunk * 24576u + (uint32_t)nt * 2048u + (uint32_t)ks * 256u +
                             (uint32_t)(n8 * 4 + ((kk & 7) >> 1)) * 8u + (uint32_t)(kk >> 3) * 4u;
        *(uint32_t*)(img + off) = hb;
        *(uint32_t*)(img + off + 12288) = lb;
    }
}

__global__ __launch_bounds__(256) void prep_x(const float* __restrict__ x) {
    const int mb = blockIdx.x >> 3, c = blockIdx.x & 7;
    uint8_t* img = d_ximg + (size_t)mb * AIMG + (size_t)c * 65536;
    for (int idx = threadIdx.x; idx < 128 * 64; idx += 256) {
        const int row = idx >> 6, kp = idx & 63, k = kp * 2;
        const int m = mb * 128 + row, t = m >> 6, b = m & 63;
        float2 v = *(const float2*)(x + ((size_t)b * SS + t) * CC + c * 128 + k);
        uint32_t hb, lb;
        cvt2(v.x, v.y, hb, lb);
        const int r16 = row >> 4, ks = k >> 4, kk = k & 15;
        const uint32_t off = (uint32_t)r16 * 4096u + (uint32_t)ks * 512u +
                             (uint32_t)((row & 7) * 4 + ((kk & 7) >> 1)) * 16u +
                             (uint32_t)(((row >> 3) & 1) + 2 * (kk >> 3)) * 4u;
        *(uint32_t*)(img + off) = hb;
        *(uint32_t*)(img + off + 32768) = lb;
    }
}

__global__ void bar_reset() {
    for (int i = threadIdx.x; i < 1032; i += 256) d_bar[i] = 0u;
}

// ---- phase A (unchanged from R10) ----
__global__ __launch_bounds__(256, 1) void gru_phaseA(const float* __restrict__ bih) {
    extern __shared__ char smem[];
    uint32_t sb = smem_u32(smem);
    const int ct = blockIdx.x, grp = blockIdx.y;
    const int tid = threadIdx.x, w = tid >> 5, lane = tid & 31;
    const uint8_t* wt = d_wimg + (size_t)ct * WTB;
    for (int c = 0; c < 8; c++)
        for (int i = tid * 16; i < 12288; i += 4096)
            cp_async16(sb + c * 12288 + i, wt + (size_t)c * 24576 + i);
    CP_COMMIT(); CP_WAIT0();
    __syncthreads();
    for (int mb = grp * 32; mb < grp * 32 + 32; mb++) {
        float acc[6][4] = {};
        gemm128(smem, sb, d_ximg + (size_t)mb * AIMG, wt, acc, w, lane);
        epiA(acc, d_g0 + (size_t)mb * 128 * G3, bih, ct, w, lane);
    }
}

// ---- phase B: persistent, 128 CTAs, zero cp.async in the step loop ----
__global__ __launch_bounds__(256, 1) void gru_phaseB(const float* __restrict__ bih,
                                                     const float* __restrict__ bhh,
                                                     float* __restrict__ out) {
    extern __shared__ char smem[];
    uint32_t sb = smem_u32(smem);
    const unsigned int nb = gridDim.x;
    const int tid = threadIdx.x, cta = blockIdx.x;
    const int w = tid >> 5, lane = tid & 31;
    const int mtile = w >> 1, ihalf = w & 1;
    const int ct = cta & 63;

    const uint8_t* wt1 = d_wimg + (size_t)(64 + cta) * WTB;   // Whh0[ct] or Whh1[ct]
    const uint8_t* wt2 = d_wimg + (size_t)(192 + ct) * WTB;   // Wih1[ct] (streamed via LDG)
    for (int c = 0; c < 8; c++)
        for (int i = tid * 16; i < 12288; i += 4096)
            cp_async16(sb + c * 12288 + i, wt1 + (size_t)c * 24576 + i);
    CP_COMMIT(); CP_WAIT0();
    __syncthreads();

    const int gidx = cta * 256 + tid, gs = (int)nb * 256;
    for (int i = gidx; i < BB * HH; i += gs) { d_h0f[0][i] = 0.f; d_h1f[0][i] = 0.f; }
    for (int i = gidx; i < (int)(HIMG / 4); i += gs) {
        ((uint32_t*)d_himg0[0])[i] = 0u;
        ((uint32_t*)d_himg1[0])[i] = 0u;
    }
    grid_sync_slot(0, nb);

    for (int t = 0; t < SS; t++) {
        const int cur = t & 1, nxt = cur ^ 1;
        {
            float acc[3][4];
            if (cta < 64) {
                gemm64_v2<true>(smem, d_himg0[cur], wt1, acc, mtile, ihalf, lane);
                epi_update<1>(acc, d_g0 + (size_t)t * BB * G3, d_h0f[cur], d_h0f[nxt],
                              d_himg0[nxt], bhh, ct, mtile, ihalf, lane);
            } else {
                gemm64_v2<true>(smem, d_himg1[cur], wt1, acc, mtile, ihalf, lane);
                epi_raw(acc, d_gh1, bhh + G3, ct, mtile, ihalf, lane);
            }
        }
        grid_sync_slot(1 + 2 * t, nb);
        if (cta < 64) {
            float acc[3][4];
            gemm64_v2<false>(smem, d_himg0[nxt], wt2, acc, mtile, ihalf, lane);
            epi_update<0>(acc, d_gh1, d_h1f[cur], d_h1f[nxt],
                          d_himg1[nxt], bih + G3, ct, mtile, ihalf, lane);
        }
        grid_sync_slot(2 + 2 * t, nb);
    }
    for (int i = gidx; i < BB * HH; i += gs) out[i] = d_h1f[0][i];
}

// ---- host launcher ----
extern "C" void kernel_launch(void* const* d_in, const int* in_sizes, int n_in,
                              void* d_out, int out_size) {
    const float* x   = (const float*)d_in[0];
    const float* wih = (const float*)d_in[1];
    const float* whh = (const float*)d_in[2];
    const float* bih = (const float*)d_in[3];
    const float* bhh = (const float*)d_in[4];
    float* out = (float*)d_out;

    cudaFuncSetAttribute(gru_phaseA, cudaFuncAttributeMaxDynamicSharedMemorySize, PA_SMEM);
    cudaFuncSetAttribute(gru_phaseB, cudaFuncAttributeMaxDynamicSharedMemorySize, PB_SMEM);

    prep_w<<<256, 256>>>(wih, whh);
    prep_x<<<2048, 256>>>(x);
    bar_reset<<<1, 256>>>();
    gru_phaseA<<<dim3(64, 8), 256, PA_SMEM>>>(bih);
    gru_phaseB<<<128, 256, PB_SMEM>>>(bih, bhh, out);
}

// round 12
// speedup vs baseline: 1.1739x; 1.0885x over previous
#include <cuda_runtime.h>
#include <cuda_bf16.h>
#include <cstdint>
#include <math.h>

#define BB 64
#define SS 512
#define CC 1024
#define HH 1024
#define G3 3072

#define WTB   196608u
#define AIMG  524288u
#define HIMG  262144u

#define PB_SMEM (98304 + 6144)          // 96KB resident W1-hi + 6KB reduction
#define SLOA  98304u
#define PA_SMEM (98304 + 24576)

__device__ __align__(16) float   d_g0[(size_t)SS * BB * G3];
__device__ __align__(16) float   d_h0f[2][BB * HH];
__device__ __align__(16) float   d_h1f[2][BB * HH];
__device__ __align__(16) float   d_gh1[BB * G3];
__device__ __align__(128) uint8_t d_wimg[256ull * WTB];   // 0-63 Wih0 | 64-127 Whh0 | 128-191 Whh1 | 192-255 Wih1
__device__ __align__(128) uint8_t d_ximg[256ull * AIMG];
__device__ __align__(128) uint8_t d_himg0[2][HIMG];
__device__ __align__(128) uint8_t d_himg1[2][HIMG];
__device__ unsigned int d_bar[1032];

__device__ __forceinline__ uint32_t smem_u32(const void* p) {
    uint32_t a;
    asm("{ .reg .u64 t; cvta.to.shared.u64 t, %1; cvt.u32.u64 %0, t; }" : "=r"(a) : "l"(p));
    return a;
}
__device__ __forceinline__ void cp_async16(uint32_t s, const void* g) {
    asm volatile("cp.async.cg.shared.global [%0], [%1], 16;" :: "r"(s), "l"(g));
}
#define CP_COMMIT() asm volatile("cp.async.commit_group;" ::: "memory")
#define CP_WAIT1()  asm volatile("cp.async.wait_group 1;" ::: "memory")
#define CP_WAIT0()  asm volatile("cp.async.wait_group 0;" ::: "memory")

__device__ __forceinline__ void mma16816(float (&d)[4], const uint32_t* a, const uint32_t* b) {
    asm volatile("mma.sync.aligned.m16n8k16.row.col.f32.bf16.bf16.f32 "
        "{%0,%1,%2,%3}, {%4,%5,%6,%7}, {%8,%9}, {%0,%1,%2,%3};"
        : "+f"(d[0]), "+f"(d[1]), "+f"(d[2]), "+f"(d[3])
        : "r"(a[0]), "r"(a[1]), "r"(a[2]), "r"(a[3]), "r"(b[0]), "r"(b[1]));
}
__device__ __forceinline__ void cvt2(float a, float b, uint32_t& hi, uint32_t& lo) {
    __nv_bfloat162 h = __floats2bfloat162_rn(a, b);
    float2 f = __bfloat1622float2(h);
    __nv_bfloat162 l = __floats2bfloat162_rn(a - f.x, b - f.y);
    hi = *(uint32_t*)&h;
    lo = *(uint32_t*)&l;
}
__device__ __forceinline__ float sigm(float x) { return 1.0f / (1.0f + __expf(-x)); }

__device__ __forceinline__ void grid_sync_slot(int slot, unsigned int nb) {
    __syncthreads();
    if (threadIdx.x == 0) {
        __threadfence();
        atomicAdd(&d_bar[slot], 1u);
        while (*((volatile unsigned int*)&d_bar[slot]) < nb) { __nanosleep(64); }
        __threadfence();
    }
    __syncthreads();
}

// ---- GEMM M=64 full (stage 1): W-hi resident, W-lo via LDG, 8 ks/warp ----
__device__ __forceinline__ void gemm64_full(const char* smem, const uint8_t* __restrict__ aimg,
        const uint8_t* __restrict__ wtile, float (&acc)[3][4], int mtile, int ihalf, int lane) {
    const uint32_t t16 = (uint32_t)lane * 16u, t8 = (uint32_t)lane * 8u;
    float a2[2][3][4];
#pragma unroll
    for (int p = 0; p < 2; p++)
#pragma unroll
        for (int j = 0; j < 3; j++)
#pragma unroll
            for (int q = 0; q < 4; q++) a2[p][j][q] = 0.f;
#pragma unroll 1
    for (int c = 0; c < 8; c++) {
        const uint8_t* ab = aimg + (size_t)c * 32768 + (uint32_t)mtile * 4096u + t16;
        const uint8_t* wb = wtile + (size_t)c * 24576 + (uint32_t)ihalf * 2048u + t8;
        const char*    rb = smem + c * 12288 + (uint32_t)ihalf * 2048u + t8;
        uint4 AH[8], AL[8];
        uint2 BH[8][3], BL[8][3];
#pragma unroll
        for (int ks = 0; ks < 8; ks++) {
            AH[ks] = *(const uint4*)(ab + ks * 512);
            AL[ks] = *(const uint4*)(ab + 16384 + ks * 512);
        }
#pragma unroll
        for (int ks = 0; ks < 8; ks++)
#pragma unroll
            for (int j = 0; j < 3; j++) {
                BL[ks][j] = *(const uint2*)(wb + 12288 + j * 4096 + ks * 256);
                BH[ks][j] = *(const uint2*)(rb + j * 4096 + ks * 256);
            }
#pragma unroll
        for (int ks = 0; ks < 8; ks++) {
            const int p = ks & 1;
#pragma unroll
            for (int j = 0; j < 3; j++) {
                mma16816(a2[p][j], (const uint32_t*)&AH[ks], (const uint32_t*)&BH[ks][j]);
                mma16816(a2[p][j], (const uint32_t*)&AH[ks], (const uint32_t*)&BL[ks][j]);
                mma16816(a2[p][j], (const uint32_t*)&AL[ks], (const uint32_t*)&BH[ks][j]);
            }
        }
    }
#pragma unroll
    for (int j = 0; j < 3; j++)
#pragma unroll
        for (int q = 0; q < 4; q++) acc[j][q] = a2[0][j][q] + a2[1][j][q];
}

// ---- GEMM M=64 K-split half (stage 2): W hi+lo via LDG, 4 ks/warp (parity kpar) ----
__device__ __forceinline__ void gemm64_half(const uint8_t* __restrict__ aimg,
        const uint8_t* __restrict__ wtile, float (&acc)[3][4], int mtile, int ihalf,
        int kpar, int lane) {
    const uint32_t t16 = (uint32_t)lane * 16u, t8 = (uint32_t)lane * 8u;
#pragma unroll
    for (int j = 0; j < 3; j++)
#pragma unroll
        for (int q = 0; q < 4; q++) acc[j][q] = 0.f;
#pragma unroll 1
    for (int c = 0; c < 8; c++) {
        const uint8_t* ab = aimg + (size_t)c * 32768 + (uint32_t)mtile * 4096u + t16;
        const uint8_t* wb = wtile + (size_t)c * 24576 + (uint32_t)ihalf * 2048u + t8;
        uint4 AH[4], AL[4];
        uint2 BH[4][3], BL[4][3];
#pragma unroll
        for (int u = 0; u < 4; u++) {
            const int ks = kpar + 2 * u;
            AH[u] = *(const uint4*)(ab + ks * 512);
            AL[u] = *(const uint4*)(ab + 16384 + ks * 512);
        }
#pragma unroll
        for (int u = 0; u < 4; u++) {
            const int ks = kpar + 2 * u;
#pragma unroll
            for (int j = 0; j < 3; j++) {
                BH[u][j] = *(const uint2*)(wb + j * 4096 + ks * 256);
                BL[u][j] = *(const uint2*)(wb + 12288 + j * 4096 + ks * 256);
            }
        }
#pragma unroll
        for (int u = 0; u < 4; u++)
#pragma unroll
            for (int j = 0; j < 3; j++) {
                mma16816(acc[j], (const uint32_t*)&AH[u], (const uint32_t*)&BH[u][j]);
                mma16816(acc[j], (const uint32_t*)&AH[u], (const uint32_t*)&BL[u][j]);
                mma16816(acc[j], (const uint32_t*)&AL[u], (const uint32_t*)&BH[u][j]);
            }
    }
}

// ---- GEMM M=128 (phase A, unchanged) ----
__device__ __forceinline__ void gemm128(char* smem, uint32_t sb,
        const uint8_t* __restrict__ aimg, const uint8_t* __restrict__ wtile,
        float (&acc)[6][4], int w, int lane) {
    const int tid = threadIdx.x;
    const uint32_t t16 = (uint32_t)lane * 16u, t8 = (uint32_t)lane * 8u;
    for (int i = tid * 16; i < 12288; i += 4096) cp_async16(sb + SLOA + i, wtile + 12288 + i);
    CP_COMMIT();
    for (int c = 0; c < 8; c++) {
        if (c) __syncthreads();
        if (c < 7) {
            const uint8_t* src = wtile + (size_t)(c + 1) * 24576 + 12288;
            uint32_t dst = sb + SLOA + (uint32_t)((c + 1) & 1) * 12288u;
            for (int i = tid * 16; i < 12288; i += 4096) cp_async16(dst + i, src + i);
            CP_COMMIT();
        }
        uint4 AH[8], AL[8];
        const uint8_t* ab = aimg + (size_t)c * 65536 + (uint32_t)w * 4096u + t16;
#pragma unroll
        for (int ks = 0; ks < 8; ks++) {
            AH[ks] = *(const uint4*)(ab + ks * 512);
            AL[ks] = *(const uint4*)(ab + 32768 + ks * 512);
        }
        if (c < 7) { CP_WAIT1(); } else { CP_WAIT0(); }
        __syncthreads();
        const char* wb = smem + c * 12288;
        const char* lb = smem + SLOA + (c & 1) * 12288;
#pragma unroll
        for (int ks = 0; ks < 8; ks++) {
#pragma unroll
            for (int nt = 0; nt < 6; nt++) {
                uint32_t bh[2], bl[2];
                *(uint2*)bh = *(const uint2*)(wb + nt * 2048 + ks * 256 + t8);
                *(uint2*)bl = *(const uint2*)(lb + nt * 2048 + ks * 256 + t8);
                mma16816(acc[nt], (const uint32_t*)&AH[ks], bh);
                mma16816(acc[nt], (const uint32_t*)&AH[ks], bl);
                mma16816(acc[nt], (const uint32_t*)&AL[ks], bh);
            }
        }
    }
    __syncthreads();
}

// ---- epilogues (unchanged) ----
template <int ACC_IS_GH>
__device__ __forceinline__ void epi_update(const float (&acc)[3][4],
        const float* __restrict__ gsrc, const float* __restrict__ hprevf,
        float* __restrict__ houtf, uint8_t* __restrict__ himg_out,
        const float* __restrict__ bias, int ct, int mtile, int ihalf, int lane) {
    const int r0 = mtile * 16 + (lane >> 2);
    const int i = ihalf * 8 + (lane & 3) * 2;
    const int hb16 = ct * 16, cb = ct * 48;
    float2 br = *(const float2*)(bias + hb16 + i);
    float2 bz = *(const float2*)(bias + HH + hb16 + i);
    float2 bn = *(const float2*)(bias + 2 * HH + hb16 + i);
    const uint32_t chb = (uint32_t)(ct >> 3) * 32768u + (uint32_t)(ct & 7) * 512u +
                         (uint32_t)mtile * 4096u + (uint32_t)lane * 16u;
#pragma unroll
    for (int rs = 0; rs < 2; rs++) {
        const int row = r0 + rs * 8, di = rs * 2;
        float ar0 = acc[0][di] + br.x, ar1 = acc[0][di + 1] + br.y;
        float az0 = acc[1][di] + bz.x, az1 = acc[1][di + 1] + bz.y;
        float an0 = acc[2][di] + bn.x, an1 = acc[2][di + 1] + bn.y;
        const float* gp = gsrc + (size_t)row * G3 + cb;
        float2 gr = *(const float2*)(gp + i);
        float2 gz = *(const float2*)(gp + 16 + i);
        float2 gn = *(const float2*)(gp + 32 + i);
        float ir0, iz0, in0, hr0, hz0, hn0, ir1, iz1, in1, hr1, hz1, hn1;
        if (ACC_IS_GH) {
            ir0 = gr.x; iz0 = gz.x; in0 = gn.x; hr0 = ar0; hz0 = az0; hn0 = an0;
            ir1 = gr.y; iz1 = gz.y; in1 = gn.y; hr1 = ar1; hz1 = az1; hn1 = an1;
        } else {
            hr0 = gr.x; hz0 = gz.x; hn0 = gn.x; ir0 = ar0; iz0 = az0; in0 = an0;
            hr1 = gr.y; hz1 = gz.y; hn1 = gn.y; ir1 = ar1; iz1 = az1; in1 = an1;
        }
        float rr0 = sigm(ir0 + hr0), zz0 = sigm(iz0 + hz0);
        float rr1 = sigm(ir1 + hr1), zz1 = sigm(iz1 + hz1);
        float nn0 = tanhf(in0 + rr0 * hn0);
        float nn1 = tanhf(in1 + rr1 * hn1);
        float2 hp = *(const float2*)(hprevf + (size_t)row * HH + hb16 + i);
        float h0v = (1.f - zz0) * nn0 + zz0 * hp.x;
        float h1v = (1.f - zz1) * nn1 + zz1 * hp.y;
        *(float2*)(houtf + (size_t)row * HH + hb16 + i) = make_float2(h0v, h1v);
        uint32_t hb, lb;
        cvt2(h0v, h1v, hb, lb);
        const uint32_t ea = chb + (uint32_t)(rs + 2 * ihalf) * 4u;
        *(uint32_t*)(himg_out + ea) = hb;
        *(uint32_t*)(himg_out + 16384 + ea) = lb;
    }
}

__device__ __forceinline__ void epi_raw(const float (&acc)[3][4], float* __restrict__ outg,
        const float* __restrict__ bias, int ct, int mtile, int ihalf, int lane) {
    const int r0 = mtile * 16 + (lane >> 2);
    const int i = ihalf * 8 + (lane & 3) * 2;
    const int hb16 = ct * 16, cb = ct * 48;
#pragma unroll
    for (int j = 0; j < 3; j++) {
        float2 bs = *(const float2*)(bias + j * HH + hb16 + i);
        *(float2*)(outg + (size_t)r0 * G3 + cb + j * 16 + i) =
            make_float2(acc[j][0] + bs.x, acc[j][1] + bs.y);
        *(float2*)(outg + (size_t)(r0 + 8) * G3 + cb + j * 16 + i) =
            make_float2(acc[j][2] + bs.x, acc[j][3] + bs.y);
    }
}

__device__ __forceinline__ void epiA(const float (&acc)[6][4], float* __restrict__ outg,
        const float* __restrict__ bias, int ct, int w, int lane) {
    const int r0 = w * 16 + (lane >> 2);
    const int cb = ct * 48, li2 = (lane & 3) * 2;
#pragma unroll
    for (int nt = 0; nt < 6; nt++) {
        const int g = nt >> 1, i = (nt & 1) * 8 + li2;
        float2 bs = *(const float2*)(bias + g * HH + ct * 16 + i);
        *(float2*)(outg + (size_t)r0 * G3 + cb + nt * 8 + li2) =
            make_float2(acc[nt][0] + bs.x, acc[nt][1] + bs.y);
        *(float2*)(outg + (size_t)(r0 + 8) * G3 + cb + nt * 8 + li2) =
            make_float2(acc[nt][2] + bs.x, acc[nt][3] + bs.y);
    }
}

// ---- prep kernels (prep_w now also resets barrier slots; bar_reset launch removed) ----
__global__ __launch_bounds__(256) void prep_w(const float* __restrict__ wih, const float* __restrict__ whh) {
    const int tile = blockIdx.x;
    if (tile == 0)
        for (int i = threadIdx.x; i < 1032; i += 256) d_bar[i] = 0u;
    const float* W;
    if (tile < 64)       W = wih;
    else if (tile < 128) W = whh;
    else if (tile < 192) W = whh + (size_t)G3 * HH;
    else                 W = wih + (size_t)G3 * CC;
    const int ct = tile & 63;
    uint8_t* img = d_wimg + (size_t)tile * WTB;
    for (int idx = threadIdx.x; idx < 48 * 512; idx += 256) {
        const int j = idx >> 9, kp = idx & 511, k = kp * 2;
        const int g = j >> 4, i2 = j & 15;
        float2 v = *(const float2*)(W + (size_t)(g * HH + ct * 16 + i2) * CC + k);
        uint32_t hb, lb;
        cvt2(v.x, v.y, hb, lb);
        const int chunk = k >> 7, ks = (k >> 4) & 7, kk = k & 15;
        const int nt = j >> 3, n8 = j & 7;
        const uint32_t off = (uint32_t)chunk * 24576u + (uint32_t)nt * 2048u + (uint32_t)ks * 256u +
                             (uint32_t)(n8 * 4 + ((kk & 7) >> 1)) * 8u + (uint32_t)(kk >> 3) * 4u;
        *(uint32_t*)(img + off) = hb;
        *(uint32_t*)(img + off + 12288) = lb;
    }
}

__global__ __launch_bounds__(256) void prep_x(const float* __restrict__ x) {
    const int mb = blockIdx.x >> 3, c = blockIdx.x & 7;
    uint8_t* img = d_ximg + (size_t)mb * AIMG + (size_t)c * 65536;
    for (int idx = threadIdx.x; idx < 128 * 64; idx += 256) {
        const int row = idx >> 6, kp = idx & 63, k = kp * 2;
        const int m = mb * 128 + row, t = m >> 6, b = m & 63;
        float2 v = *(const float2*)(x + ((size_t)b * SS + t) * CC + c * 128 + k);
        uint32_t hb, lb;
        cvt2(v.x, v.y, hb, lb);
        const int r16 = row >> 4, ks = k >> 4, kk = k & 15;
        const uint32_t off = (uint32_t)r16 * 4096u + (uint32_t)ks * 512u +
                             (uint32_t)((row & 7) * 4 + ((kk & 7) >> 1)) * 16u +
                             (uint32_t)(((row >> 3) & 1) + 2 * (kk >> 3)) * 4u;
        *(uint32_t*)(img + off) = hb;
        *(uint32_t*)(img + off + 32768) = lb;
    }
}

// ---- phase A (unchanged) ----
__global__ __launch_bounds__(256, 1) void gru_phaseA(const float* __restrict__ bih) {
    extern __shared__ char smem[];
    uint32_t sb = smem_u32(smem);
    const int ct = blockIdx.x, grp = blockIdx.y;
    const int tid = threadIdx.x, w = tid >> 5, lane = tid & 31;
    const uint8_t* wt = d_wimg + (size_t)ct * WTB;
    for (int c = 0; c < 8; c++)
        for (int i = tid * 16; i < 12288; i += 4096)
            cp_async16(sb + c * 12288 + i, wt + (size_t)c * 24576 + i);
    CP_COMMIT(); CP_WAIT0();
    __syncthreads();
    for (int mb = grp * 32; mb < grp * 32 + 32; mb++) {
        float acc[6][4] = {};
        gemm128(smem, sb, d_ximg + (size_t)mb * AIMG, wt, acc, w, lane);
        epiA(acc, d_g0 + (size_t)mb * 128 * G3, bih, ct, w, lane);
    }
}

// ---- phase B: persistent, 128 CTAs; stage2 spread over all CTAs via ihalf + K-split warps ----
__global__ __launch_bounds__(256, 1) void gru_phaseB(const float* __restrict__ bih,
                                                     const float* __restrict__ bhh,
                                                     float* __restrict__ out) {
    extern __shared__ char smem[];
    uint32_t sb = smem_u32(smem);
    const unsigned int nb = gridDim.x;
    const int tid = threadIdx.x, cta = blockIdx.x;
    const int w = tid >> 5, lane = tid & 31;
    const int mtile = w >> 1, wlow = w & 1;     // stage1: wlow=ihalf ; stage2: wlow=kpar
    const int ct = cta & 63;

    const uint8_t* wt1 = d_wimg + (size_t)(64 + cta) * WTB;   // Whh0[ct] or Whh1[ct]
    const uint8_t* wt2 = d_wimg + (size_t)(192 + ct) * WTB;   // Wih1[ct] (LDG-streamed)
    for (int c = 0; c < 8; c++)
        for (int i = tid * 16; i < 12288; i += 4096)
            cp_async16(sb + c * 12288 + i, wt1 + (size_t)c * 24576 + i);
    CP_COMMIT(); CP_WAIT0();
    __syncthreads();

    const int gidx = cta * 256 + tid, gs = (int)nb * 256;
    for (int i = gidx; i < BB * HH; i += gs) { d_h0f[0][i] = 0.f; d_h1f[0][i] = 0.f; }
    for (int i = gidx; i < (int)(HIMG / 4); i += gs) {
        ((uint32_t*)d_himg0[0])[i] = 0u;
        ((uint32_t*)d_himg1[0])[i] = 0u;
    }
    grid_sync_slot(0, nb);

    float* red = (float*)(smem + 98304);
    for (int t = 0; t < SS; t++) {
        const int cur = t & 1, nxt = cur ^ 1;
        // ---- stage 1: 128 full jobs (layer0 update | layer1 gh) ----
        {
            float acc[3][4];
            if (cta < 64) {
                gemm64_full(smem, d_himg0[cur], wt1, acc, mtile, wlow, lane);
                epi_update<1>(acc, d_g0 + (size_t)t * BB * G3, d_h0f[cur], d_h0f[nxt],
                              d_himg0[nxt], bhh, ct, mtile, wlow, lane);
            } else {
                gemm64_full(smem, d_himg1[cur], wt1, acc, mtile, wlow, lane);
                epi_raw(acc, d_gh1, bhh + G3, ct, mtile, wlow, lane);
            }
        }
        grid_sync_slot(1 + 2 * t, nb);
        // ---- stage 2: 64 jobs split over 128 CTAs (cih = N-half) + K-parity warps ----
        {
            const int cih = cta >> 6;
            float acc[3][4];
            gemm64_half(d_himg0[nxt], wt2, acc, mtile, cih, wlow, lane);
            float* rp = red + (mtile * 32 + lane) * 12;
            if (wlow == 1) {
                *(float4*)(rp + 0) = make_float4(acc[0][0], acc[0][1], acc[0][2], acc[0][3]);
                *(float4*)(rp + 4) = make_float4(acc[1][0], acc[1][1], acc[1][2], acc[1][3]);
                *(float4*)(rp + 8) = make_float4(acc[2][0], acc[2][1], acc[2][2], acc[2][3]);
            }
            __syncthreads();
            if (wlow == 0) {
#pragma unroll
                for (int j = 0; j < 3; j++) {
                    float4 pv = *(const float4*)(rp + j * 4);
                    acc[j][0] += pv.x; acc[j][1] += pv.y; acc[j][2] += pv.z; acc[j][3] += pv.w;
                }
                epi_update<0>(acc, d_gh1, d_h1f[cur], d_h1f[nxt],
                              d_himg1[nxt], bih + G3, ct, mtile, cih, lane);
            }
        }
        grid_sync_slot(2 + 2 * t, nb);
    }
    for (int i = gidx; i < BB * HH; i += gs) out[i] = d_h1f[0][i];
}

// ---- host launcher (4 launches: ncu captures #4 = phaseB) ----
extern "C" void kernel_launch(void* const* d_in, const int* in_sizes, int n_in,
                              void* d_out, int out_size) {
    const float* x   = (const float*)d_in[0];
    const float* wih = (const float*)d_in[1];
    const float* whh = (const float*)d_in[2];
    const float* bih = (const float*)d_in[3];
    const float* bhh = (const float*)d_in[4];
    float* out = (float*)d_out;

    cudaFuncSetAttribute(gru_phaseA, cudaFuncAttributeMaxDynamicSharedMemorySize, PA_SMEM);
    cudaFuncSetAttribute(gru_phaseB, cudaFuncAttributeMaxDynamicSharedMemorySize, PB_SMEM);

    prep_w<<<256, 256>>>(wih, whh);
    prep_x<<<2048, 256>>>(x);
    gru_phaseA<<<dim3(64, 8), 256, PA_SMEM>>>(bih);
    gru_phaseB<<<128, 256, PB_SMEM>>>(bih, bhh, out);
}